// round 8
// baseline (speedup 1.0000x reference)
#include <cuda_runtime.h>
#include <cuda_fp16.h>
#include <stdint.h>
#include <math.h>

#define MTOT 16384
#define DIN  1024
#define DSZ  256
#define KCH  64            // k-halfs per pipeline chunk (128B data/row)
#define LDR  144           // padded SMEM row stride (128 data + 16 pad)
#define PL   (128 * LDR)   // 18432 bytes per plane
#define STG  (2 * PL)      // A+B planes per stage = 36864
#define NST  3
#define SMEM_SZ (NST * STG)   // 110592 -> 2 CTAs/SM (221184 < 228KB)

// ---------------- scratch (__device__ globals; no allocations) ----------------
__device__ __half xh_g[(size_t)MTOT * DIN];
__device__ __half w1f16_g[(size_t)12 * DSZ * DIN];
__device__ __half w2f16_g[(size_t)4 * DSZ * DSZ];
__device__ __half g1f16_g[(size_t)4 * MTOT * DSZ];
__device__ __half dre_g[(size_t)4 * MTOT * DSZ];
__device__ __half dim_g[(size_t)4 * MTOT * DSZ];
__device__ float omg_g[(size_t)4 * MTOT * DSZ];
__device__ float2 Aseg_g[256 * 256];
__device__ float2 Hseg_g[256 * 256];
__device__ int    flag_g[256];

// ---------------- PTX helpers (baseline ISA only) ------------------------------
__device__ __forceinline__ uint32_t smem_u32(const void* p) {
    uint32_t a;
    asm("{ .reg .u64 t; cvta.to.shared.u64 t, %1; cvt.u32.u64 %0, t; }" : "=r"(a) : "l"(p));
    return a;
}
__device__ __forceinline__ void cpa16(uint32_t dst, const void* src) {
    asm volatile("cp.async.cg.shared.global [%0], [%1], 16;" :: "r"(dst), "l"(src));
}
__device__ __forceinline__ void cpa_commit() {
    asm volatile("cp.async.commit_group;");
}
template<int N> __device__ __forceinline__ void cpa_wait() {
    asm volatile("cp.async.wait_group %0;" :: "n"(N));
}
__device__ __forceinline__ void ldsm4(uint32_t r[4], uint32_t addr) {
    asm volatile("ldmatrix.sync.aligned.m8n8.x4.shared.b16 {%0,%1,%2,%3}, [%4];"
        : "=r"(r[0]), "=r"(r[1]), "=r"(r[2]), "=r"(r[3]) : "r"(addr));
}
__device__ __forceinline__ void mma_f16(float c[4], const uint32_t a[4], const uint32_t b[2]) {
    asm volatile("mma.sync.aligned.m16n8k16.row.col.f32.f16.f16.f32 "
        "{%0,%1,%2,%3}, {%4,%5,%6,%7}, {%8,%9}, {%0,%1,%2,%3};"
        : "+f"(c[0]), "+f"(c[1]), "+f"(c[2]), "+f"(c[3])
        : "r"(a[0]), "r"(a[1]), "r"(a[2]), "r"(a[3]), "r"(b[0]), "r"(b[1]));
}

// ---------------- GEMM pipeline (128x128 tile, KCH=64, NST=3, 2-deep) ----------
// Per iter: wait<1> (only chunk ch must land; ch+1 stays in flight); sync;
// issue ch+2 into stage (ch+2)%3 (distinct from ch%3 and (ch+1)%3); compute ch.
template<int NCH>
__device__ __forceinline__ void gemm_pipeline(
    const __half* __restrict__ gA, const __half* __restrict__ gB,
    const int ldk, uint32_t s0, float acc[2][8][4])
{
    const int tid = threadIdx.x;

    auto issue = [&](int st, int k0) {
        uint32_t base = s0 + st * STG;
#pragma unroll
        for (int it = 0; it < 4; it++) {
            int q = tid + it * 256;
            int r = q >> 3, c = q & 7;
            uint32_t off = base + r * LDR + c * 16;
            size_t go = (size_t)r * ldk + k0 + c * 8;
            cpa16(off,      gA + go);
            cpa16(off + PL, gB + go);
        }
        cpa_commit();
    };

#pragma unroll
    for (int i = 0; i < 2; i++)
#pragma unroll
        for (int j = 0; j < 8; j++)
#pragma unroll
            for (int k = 0; k < 4; k++) acc[i][j][k] = 0.f;

    issue(0, 0);
    if (NCH > 1) issue(1, KCH);

    const int lane = tid & 31, warp = tid >> 5;
    const int wm = warp & 3, wn = warp >> 2;
    const uint32_t aBase = (uint32_t)(wm * 32 + (lane & 15)) * LDR + (lane >> 4) * 16;
    const uint32_t bBase = (uint32_t)(wn * 64 + (lane & 7) + ((lane & 16) >> 1)) * LDR
                         + ((lane >> 3) & 1) * 16;

    int st = 0;                       // ch % 3, tracked incrementally
    for (int ch = 0; ch < NCH; ch++) {
        if (ch >= NCH - 1) cpa_wait<0>(); else cpa_wait<1>();
        __syncthreads();
        if (ch + 2 < NCH) {
            int st2 = st + 2; if (st2 >= 3) st2 -= 3;
            issue(st2, (ch + 2) * KCH);
        }
        const uint32_t sb = s0 + st * STG;
#pragma unroll
        for (int ks = 0; ks < 4; ks++) {
            uint32_t ah[2][4], bb[4][4];
#pragma unroll
            for (int mi = 0; mi < 2; mi++)
                ldsm4(ah[mi], sb + aBase + mi * (16 * LDR) + ks * 32);
#pragma unroll
            for (int nf4 = 0; nf4 < 4; nf4++)
                ldsm4(bb[nf4], sb + PL + bBase + nf4 * (16 * LDR) + ks * 32);
#pragma unroll
            for (int mi = 0; mi < 2; mi++)
#pragma unroll
                for (int nf = 0; nf < 8; nf++)
                    mma_f16(acc[mi][nf], ah[mi], &bb[nf >> 1][(nf & 1) * 2]);
        }
        if (++st >= 3) st = 0;
    }
}

// ---------------- GEMM 1: x @ {Wg1,Wdr,Wdi} -----------------------------------
__global__ __launch_bounds__(256) void gemm1_k(
    const float* __restrict__ bg1, const float* __restrict__ bdr, const float* __restrict__ bdi)
{
    extern __shared__ char sm[];
    uint32_t s0 = smem_u32(sm);

    const int mbase = blockIdx.x * 128;
    const int nb = blockIdx.y;
    const int mat = nb >> 3;
    const int s = (nb >> 1) & 3;
    const int dbase = (nb & 1) * 128;

    const __half* gA = xh_g + (size_t)mbase * DIN;
    const __half* gB = w1f16_g + ((size_t)(mat * 4 + s) * DSZ + dbase) * DIN;

    float acc[2][8][4];
    gemm_pipeline<DIN / KCH>(gA, gB, DIN, s0, acc);

    const int lane = threadIdx.x & 31, warp = threadIdx.x >> 5;
    const int wm = warp & 3, wn = warp >> 2;
    const int r0 = mbase + wm * 32 + (lane >> 2);
    const int c0 = wn * 64 + (lane & 3) * 2;
    const float* bias = (mat == 0 ? bg1 : (mat == 1 ? bdr : bdi)) + s * DSZ + dbase;
    __half* op = (mat == 0 ? g1f16_g : (mat == 1 ? dre_g : dim_g)) + (size_t)s * MTOT * DSZ;
    const bool rl = (mat == 0);

#pragma unroll
    for (int mi = 0; mi < 2; mi++)
#pragma unroll
        for (int nf = 0; nf < 8; nf++) {
            int col = c0 + nf * 8;
            float b0 = bias[col], b1 = bias[col + 1];
#pragma unroll
            for (int hh = 0; hh < 2; hh++) {
                int r = r0 + mi * 16 + hh * 8;
                float v0 = acc[mi][nf][hh * 2 + 0] + b0;
                float v1 = acc[mi][nf][hh * 2 + 1] + b1;
                if (rl) { v0 = fmaxf(v0, 0.f); v1 = fmaxf(v1, 0.f); }
                *(__half2*)(op + (size_t)r * DSZ + dbase + col) =
                    __halves2half2(__float2half_rn(v0), __float2half_rn(v1));
            }
        }
}

// ---------------- GEMM 2: omg = 1 - sigmoid(g1 @ Wg2 + bg2) --------------------
__global__ __launch_bounds__(256) void gemm2_k(const float* __restrict__ bg2)
{
    extern __shared__ char sm[];
    uint32_t s0 = smem_u32(sm);

    const int mbase = blockIdx.x * 128;
    const int s = blockIdx.y >> 1;
    const int dbase = (blockIdx.y & 1) * 128;

    const __half* gA = g1f16_g + ((size_t)s * MTOT + mbase) * DSZ;
    const __half* gB = w2f16_g + ((size_t)s * DSZ + dbase) * DSZ;

    float acc[2][8][4];
    gemm_pipeline<DSZ / KCH>(gA, gB, DSZ, s0, acc);

    const int lane = threadIdx.x & 31, warp = threadIdx.x >> 5;
    const int wm = warp & 3, wn = warp >> 2;
    const int r0 = mbase + wm * 32 + (lane >> 2);
    const int c0 = wn * 64 + (lane & 3) * 2;
    const float* bias = bg2 + s * DSZ + dbase;
    float* op = omg_g + (size_t)s * MTOT * DSZ;

#pragma unroll
    for (int mi = 0; mi < 2; mi++)
#pragma unroll
        for (int nf = 0; nf < 8; nf++) {
            int col = c0 + nf * 8;
            float b0 = bias[col], b1 = bias[col + 1];
#pragma unroll
            for (int hh = 0; hh < 2; hh++) {
                int r = r0 + mi * 16 + hh * 8;
                float2 v;
                v.x = 1.0f / (1.0f + expf(acc[mi][nf][hh * 2 + 0] + b0));
                v.y = 1.0f / (1.0f + expf(acc[mi][nf][hh * 2 + 1] + b1));
                *(float2*)(op + (size_t)r * DSZ + dbase + col) = v;
            }
        }
}

// ---------------- conversion kernels -------------------------------------------
__global__ __launch_bounds__(256) void conv_x_k(const float* __restrict__ x) {
    size_t i = ((size_t)blockIdx.x * 256 + threadIdx.x) * 4;
    float4 v = *(const float4*)(x + i);
    union { __half h[4]; uint2 u; } p;
    p.h[0] = __float2half_rn(v.x);
    p.h[1] = __float2half_rn(v.y);
    p.h[2] = __float2half_rn(v.z);
    p.h[3] = __float2half_rn(v.w);
    *(uint2*)(xh_g + i) = p.u;
}

__global__ void conv_w1_all_k(const float* __restrict__ Wg1,
                              const float* __restrict__ Wdr,
                              const float* __restrict__ Wdi) {
    __shared__ float t[32][33];
    int z = blockIdx.z;
    const float* base = (z < 4 ? Wg1 : (z < 8 ? Wdr : Wdi));
    const float* sp = base + (size_t)(z & 3) * DIN * DSZ;
    int tx = threadIdx.x, ty = threadIdx.y;
    int k0 = blockIdx.x * 32, d0 = blockIdx.y * 32;
#pragma unroll
    for (int i = 0; i < 4; i++)
        t[ty + i * 8][tx] = sp[(size_t)(k0 + ty + i * 8) * DSZ + d0 + tx];
    __syncthreads();
    __half* oh = w1f16_g + (size_t)z * DSZ * DIN;
#pragma unroll
    for (int i = 0; i < 4; i++) {
        int n = d0 + ty + i * 8, k = k0 + tx;
        oh[(size_t)n * DIN + k] = __float2half_rn(t[tx][ty + i * 8]);
    }
}

__global__ void conv_w2_k(const float* __restrict__ src) {
    __shared__ float t[32][33];
    int z = blockIdx.z;
    const float* sp = src + (size_t)z * DSZ * DSZ;
    int tx = threadIdx.x, ty = threadIdx.y;
    int k0 = blockIdx.x * 32, d0 = blockIdx.y * 32;
#pragma unroll
    for (int i = 0; i < 4; i++)
        t[ty + i * 8][tx] = sp[(size_t)(k0 + ty + i * 8) * DSZ + d0 + tx];
    __syncthreads();
    __half* oh = w2f16_g + (size_t)z * DSZ * DSZ;
#pragma unroll
    for (int i = 0; i < 4; i++) {
        int n = d0 + ty + i * 8, k = k0 + tx;
        oh[(size_t)n * DSZ + k] = __float2half_rn(t[tx][ty + i * 8]);
    }
}

// ---------------- fused single-pass scan with aggregate lookback ----------------
// 256 blocks = (b,s,seg), all resident in one wave (no deadlock). Each block:
//   phase A: local scan -> publish (A,H) aggregate + flag
//   lookback: poll segs 0..seg-1 of same (b,s), fold prefix
//   phase B: rerun recurrence from prefix, write output (inputs L2-hot from A)
struct ScanConsts { float abr[4], abi[4], bsc[4]; };

__global__ __launch_bounds__(256) void scan_fused(float* __restrict__ out, ScanConsts c)
{
    const int idx = blockIdx.x;                 // b*64 + s*16 + seg
    const int seg = idx & 15, s = (idx >> 4) & 3, b = idx >> 6;
    const int d = threadIdx.x;
    const float abr = c.abr[s], abi = c.abi[s], bs = c.bsc[s];
    const size_t base = ((size_t)s * MTOT + (size_t)b * 4096 + seg * 256) * DSZ + d;

    // phase A: local segment scan
    float Ar = 1.f, Ai = 0.f, Hr = 0.f, Hi = 0.f;
#pragma unroll 4
    for (int t = 0; t < 256; t++) {
        size_t off = base + (size_t)t * DSZ;
        float w  = omg_g[off];
        float xr = __half2float(dre_g[off]);
        float xi = __half2float(dim_g[off]);
        float ar = w * abr, ai = w * abi, wb = w * bs;
        float br = wb * xr, bi = wb * xi;
        float nHr = fmaf(ar, Hr, fmaf(-ai, Hi, br));
        float nHi = fmaf(ar, Hi, fmaf( ai, Hr, bi));
        float nAr = fmaf(ar, Ar, -ai * Ai);
        float nAi = fmaf(ar, Ai,  ai * Ar);
        Hr = nHr; Hi = nHi; Ar = nAr; Ai = nAi;
    }
    Aseg_g[idx * 256 + d] = make_float2(Ar, Ai);
    Hseg_g[idx * 256 + d] = make_float2(Hr, Hi);
    __threadfence();
    __syncthreads();
    if (d == 0) atomicExch(&flag_g[idx], 1);

    // lookback: prefix over predecessors in this (b,s) row, ascending
    float cr = 0.f, ci = 0.f;
    const int rowbase = idx - seg;
    for (int g = 0; g < seg; g++) {
        const int pidx = rowbase + g;
        if (d == 0) {
            while (((volatile int*)flag_g)[pidx] == 0) { }
        }
        __syncthreads();
        __threadfence();
        float2 A = Aseg_g[pidx * 256 + d];
        float2 H = Hseg_g[pidx * 256 + d];
        float ncr = fmaf(A.x, cr, fmaf(-A.y, ci, H.x));
        float nci = fmaf(A.x, ci, fmaf( A.y, cr, H.y));
        cr = ncr; ci = nci;
    }

    // phase B: output pass
    float hr = cr, hi = ci;
    float* op = out + ((size_t)b * 4096 + seg * 256) * 2048 + (size_t)s * 512 + d;
#pragma unroll 4
    for (int t = 0; t < 256; t++) {
        size_t off = base + (size_t)t * DSZ;
        float w  = omg_g[off];
        float xr = __half2float(dre_g[off]);
        float xi = __half2float(dim_g[off]);
        float ar = w * abr, ai = w * abi, wb = w * bs;
        float br = wb * xr, bi = wb * xi;
        float nhr = fmaf(ar, hr, fmaf(-ai, hi, br));
        float nhi = fmaf(ar, hi, fmaf( ai, hr, bi));
        hr = nhr; hi = nhi;
        op[(size_t)t * 2048]       = hr;
        op[(size_t)t * 2048 + 256] = hi;
    }
}

// ---------------- host ----------------------------------------------------------
extern "C" void kernel_launch(void* const* d_in, const int* in_sizes, int n_in,
                              void* d_out, int out_size)
{
    const float* x   = (const float*)d_in[0];
    const float* Wg1 = (const float*)d_in[1];
    const float* bg1 = (const float*)d_in[2];
    const float* Wg2 = (const float*)d_in[3];
    const float* bg2 = (const float*)d_in[4];
    const float* Wdr = (const float*)d_in[5];
    const float* bdr = (const float*)d_in[6];
    const float* Wdi = (const float*)d_in[7];
    const float* bdi = (const float*)d_in[8];
    float* out = (float*)d_out;

    cudaFuncSetAttribute(gemm1_k, cudaFuncAttributeMaxDynamicSharedMemorySize, SMEM_SZ);
    cudaFuncSetAttribute(gemm2_k, cudaFuncAttributeMaxDynamicSharedMemorySize, SMEM_SZ);

    void* flagAddr = nullptr;
    cudaGetSymbolAddress(&flagAddr, flag_g);
    cudaMemsetAsync(flagAddr, 0, 256 * sizeof(int));

    conv_x_k<<<(int)(((size_t)MTOT * DIN) / 1024), 256>>>(x);
    dim3 tb(32, 8);
    conv_w1_all_k<<<dim3(32, 8, 12), tb>>>(Wg1, Wdr, Wdi);
    conv_w2_k<<<dim3(8, 8, 4), tb>>>(Wg2);

    gemm1_k<<<dim3(MTOT / 128, 24), 256, SMEM_SZ>>>(bg1, bdr, bdi);
    gemm2_k<<<dim3(MTOT / 128, 8), 256, SMEM_SZ>>>(bg2);

    ScanConsts c;
    const double r [4] = {1.0, 0.999, 0.9495, 0.9};
    const double th[4] = {0.0, 0.01,  0.505,  1.0};
    for (int s = 0; s < 4; s++) {
        c.abr[s] = (float)(r[s] * cos(th[s]));
        c.abi[s] = (float)(r[s] * sin(th[s]));
        c.bsc[s] = (float)((r[s] >= 1.0) ? (1.0 / 16.0) : (1.0 - r[s]));
    }
    scan_fused<<<256, 256>>>(out, c);
}

// round 10
// speedup vs baseline: 1.2700x; 1.2700x over previous
#include <cuda_runtime.h>
#include <cuda_fp16.h>
#include <stdint.h>
#include <math.h>

#define MTOT 16384
#define DIN  1024
#define DSZ  256
#define KCH  64            // k-halfs per chunk
#define LDR  144           // B smem row stride (128 data + 16 pad)
#define PLB  (128 * LDR)   // 18432 bytes: one B stage (128 n-rows)
#define NST  3
#define SMEM_SZ (NST * PLB)   // 55296 -> 2 CTAs/SM easily

// ---------------- scratch (__device__ globals; no allocations) ----------------
__device__ uint4  xp_g[(size_t)1024 * 64 * 32];      // x fragment-packed: [band][k16][lane]
__device__ __half w1f16_g[(size_t)12 * DSZ * DIN];   // [mat*4+s][n=d][k]
__device__ __half w2f16_g[(size_t)4 * DSZ * DSZ];    // [s][n=e][k]
__device__ uint4  g1p_g[(size_t)4 * 1024 * 16 * 32]; // g1 fragment-packed: [s][band][k16][lane]
__device__ __half dre_g[(size_t)4 * MTOT * DSZ];
__device__ __half dim_g[(size_t)4 * MTOT * DSZ];
__device__ float  omg_g[(size_t)4 * MTOT * DSZ];
__device__ float2 Aseg_g[256 * 256];
__device__ float2 Hseg_g[256 * 256];
__device__ float2 Ini_g [256 * 256];

// ---------------- helpers -------------------------------------------------------
__device__ __forceinline__ uint32_t pack_h2(float a, float b) {
    union { __half2 h; uint32_t u; } p;
    p.h = __halves2half2(__float2half_rn(a), __float2half_rn(b));
    return p.u;
}
__device__ __forceinline__ uint32_t smem_u32(const void* p) {
    uint32_t a;
    asm("{ .reg .u64 t; cvta.to.shared.u64 t, %1; cvt.u32.u64 %0, t; }" : "=r"(a) : "l"(p));
    return a;
}
__device__ __forceinline__ void cpa16(uint32_t dst, const void* src) {
    asm volatile("cp.async.cg.shared.global [%0], [%1], 16;" :: "r"(dst), "l"(src));
}
__device__ __forceinline__ void cpa_commit() {
    asm volatile("cp.async.commit_group;");
}
template<int N> __device__ __forceinline__ void cpa_wait() {
    asm volatile("cp.async.wait_group %0;" :: "n"(N));
}
__device__ __forceinline__ void ldsm4(uint32_t r[4], uint32_t addr) {
    asm volatile("ldmatrix.sync.aligned.m8n8.x4.shared.b16 {%0,%1,%2,%3}, [%4];"
        : "=r"(r[0]), "=r"(r[1]), "=r"(r[2]), "=r"(r[3]) : "r"(addr));
}
__device__ __forceinline__ void mma_f16u(float c[4], uint32_t a0, uint32_t a1, uint32_t a2, uint32_t a3,
                                         const uint32_t b[2]) {
    asm volatile("mma.sync.aligned.m16n8k16.row.col.f32.f16.f16.f32 "
        "{%0,%1,%2,%3}, {%4,%5,%6,%7}, {%8,%9}, {%0,%1,%2,%3};"
        : "+f"(c[0]), "+f"(c[1]), "+f"(c[2]), "+f"(c[3])
        : "r"(a0), "r"(a1), "r"(a2), "r"(a3), "r"(b[0]), "r"(b[1]));
}

// ---------------- GEMM pipeline: A fragment-direct from global, B via smem -----
// C[128,128]; 8 warps (4m x 2n). A-frags: one uint4/lane per (band, k16).
template<int NCH, int NK16>
__device__ __forceinline__ void gemm_pipeline_ad(
    const uint4* __restrict__ pA0,   // frag stream for band(mi=0), indexed by k16*32
    const uint4* __restrict__ pA1,   // band(mi=1)
    const __half* __restrict__ gB, const int ldk, uint32_t s0, uint32_t bBase,
    float acc[2][8][4])
{
    const int tid = threadIdx.x;

    auto issueB = [&](int st, int k0) {
        uint32_t base = s0 + st * PLB;
#pragma unroll
        for (int it = 0; it < 4; it++) {
            int q = tid + it * 256;
            int r = q >> 3, c = q & 7;
            cpa16(base + r * LDR + c * 16, gB + (size_t)r * ldk + k0 + c * 8);
        }
        cpa_commit();
    };

#pragma unroll
    for (int i = 0; i < 2; i++)
#pragma unroll
        for (int j = 0; j < 8; j++)
#pragma unroll
            for (int k = 0; k < 4; k++) acc[i][j][k] = 0.f;

    issueB(0, 0);
    if (NCH > 1) issueB(1, KCH);

    int st = 0;
    for (int ch = 0; ch < NCH; ch++) {
        if (ch >= NCH - 1) cpa_wait<0>(); else cpa_wait<1>();
        __syncthreads();
        if (ch + 2 < NCH) {
            int st2 = st + 2; if (st2 >= 3) st2 -= 3;
            issueB(st2, (ch + 2) * KCH);
        }
        const uint32_t sb = s0 + st * PLB;
#pragma unroll
        for (int ks = 0; ks < 4; ks++) {
            const int k16 = ch * 4 + ks;
            uint4 a0 = pA0[(size_t)k16 * 32];
            uint4 a1 = pA1[(size_t)k16 * 32];
            uint32_t bb[4][4];
#pragma unroll
            for (int nf4 = 0; nf4 < 4; nf4++)
                ldsm4(bb[nf4], sb + bBase + nf4 * (16 * LDR) + ks * 32);
#pragma unroll
            for (int nf = 0; nf < 8; nf++) {
                const uint32_t* bp = &bb[nf >> 1][(nf & 1) * 2];
                mma_f16u(acc[0][nf], a0.x, a0.y, a0.z, a0.w, bp);
                mma_f16u(acc[1][nf], a1.x, a1.y, a1.z, a1.w, bp);
            }
        }
        if (++st >= 3) st = 0;
    }
}

// ---------------- GEMM 1: x @ {Wg1,Wdr,Wdi} -----------------------------------
__global__ __launch_bounds__(256, 2) void gemm1_k(
    const float* __restrict__ bg1, const float* __restrict__ bdr, const float* __restrict__ bdi)
{
    extern __shared__ char sm[];
    uint32_t s0 = smem_u32(sm);

    const int mbase = blockIdx.x * 128;
    const int nb = blockIdx.y;                 // 0..23
    const int mat = nb >> 3;
    const int s = (nb >> 1) & 3;
    const int dbase = (nb & 1) * 128;

    const int lane = threadIdx.x & 31, warp = threadIdx.x >> 5;
    const int wm = warp & 3, wn = warp >> 2;
    const int band0 = (mbase >> 4) + wm * 2;

    const uint4* pA0 = xp_g + ((size_t)band0 * 64) * 32 + lane;
    const uint4* pA1 = xp_g + ((size_t)(band0 + 1) * 64) * 32 + lane;
    const __half* gB = w1f16_g + ((size_t)(mat * 4 + s) * DSZ + dbase) * DIN;
    const uint32_t bBase = (uint32_t)(wn * 64 + (lane & 7) + ((lane & 16) >> 1)) * LDR
                         + ((lane >> 3) & 1) * 16;

    float acc[2][8][4];
    gemm_pipeline_ad<DIN / KCH, 64>(pA0, pA1, gB, DIN, s0, bBase, acc);

    const int c0 = wn * 64 + (lane & 3) * 2;
    const float* bias = (mat == 0 ? bg1 : (mat == 1 ? bdr : bdi)) + s * DSZ + dbase;

    if (mat == 0) {
        // write g1 fragment-packed (epilogue C-frag == gemm2 A-frag layout)
        uint4* gp = g1p_g + ((size_t)s * 1024 * 16) * 32;
#pragma unroll
        for (int mi = 0; mi < 2; mi++) {
            const int band = band0 + mi;
#pragma unroll
            for (int p = 0; p < 4; p++) {
                const int nf = 2 * p;
                const int col = c0 + nf * 8;
                float b0 = bias[col],      b1 = bias[col + 1];
                float b2 = bias[col + 8],  b3 = bias[col + 9];
                uint4 w;
                w.x = pack_h2(fmaxf(acc[mi][nf][0] + b0, 0.f),
                              fmaxf(acc[mi][nf][1] + b1, 0.f));
                w.y = pack_h2(fmaxf(acc[mi][nf][2] + b0, 0.f),
                              fmaxf(acc[mi][nf][3] + b1, 0.f));
                w.z = pack_h2(fmaxf(acc[mi][nf + 1][0] + b2, 0.f),
                              fmaxf(acc[mi][nf + 1][1] + b3, 0.f));
                w.w = pack_h2(fmaxf(acc[mi][nf + 1][2] + b2, 0.f),
                              fmaxf(acc[mi][nf + 1][3] + b3, 0.f));
                const int k16 = (dbase + wn * 64 + nf * 8) >> 4;
                gp[((size_t)band * 16 + k16) * 32 + lane] = w;
            }
        }
    } else {
        const int r0 = mbase + wm * 32 + (lane >> 2);
        __half* op = (mat == 1 ? dre_g : dim_g) + (size_t)s * MTOT * DSZ;
#pragma unroll
        for (int mi = 0; mi < 2; mi++)
#pragma unroll
            for (int nf = 0; nf < 8; nf++) {
                int col = c0 + nf * 8;
                float b0 = bias[col], b1 = bias[col + 1];
#pragma unroll
                for (int hh = 0; hh < 2; hh++) {
                    int r = r0 + mi * 16 + hh * 8;
                    union { __half2 h; uint32_t u; } pk;
                    pk.u = pack_h2(acc[mi][nf][hh * 2 + 0] + b0,
                                   acc[mi][nf][hh * 2 + 1] + b1);
                    *(__half2*)(op + (size_t)r * DSZ + dbase + col) = pk.h;
                }
            }
    }
}

// ---------------- GEMM 2: omg = 1 - sigmoid(g1 @ Wg2 + bg2) --------------------
__global__ __launch_bounds__(256, 2) void gemm2_k(const float* __restrict__ bg2)
{
    extern __shared__ char sm[];
    uint32_t s0 = smem_u32(sm);

    const int mbase = blockIdx.x * 128;
    const int s = blockIdx.y >> 1;
    const int dbase = (blockIdx.y & 1) * 128;

    const int lane = threadIdx.x & 31, warp = threadIdx.x >> 5;
    const int wm = warp & 3, wn = warp >> 2;
    const int band0 = (mbase >> 4) + wm * 2;

    const uint4* pA0 = g1p_g + ((size_t)(s * 1024 + band0) * 16) * 32 + lane;
    const uint4* pA1 = g1p_g + ((size_t)(s * 1024 + band0 + 1) * 16) * 32 + lane;
    const __half* gB = w2f16_g + ((size_t)s * DSZ + dbase) * DSZ;
    const uint32_t bBase = (uint32_t)(wn * 64 + (lane & 7) + ((lane & 16) >> 1)) * LDR
                         + ((lane >> 3) & 1) * 16;

    float acc[2][8][4];
    gemm_pipeline_ad<DSZ / KCH, 16>(pA0, pA1, gB, DSZ, s0, bBase, acc);

    const int r0 = mbase + wm * 32 + (lane >> 2);
    const int c0 = wn * 64 + (lane & 3) * 2;
    const float* bias = bg2 + s * DSZ + dbase;
    float* op = omg_g + (size_t)s * MTOT * DSZ;

#pragma unroll
    for (int mi = 0; mi < 2; mi++)
#pragma unroll
        for (int nf = 0; nf < 8; nf++) {
            int col = c0 + nf * 8;
            float b0 = bias[col], b1 = bias[col + 1];
#pragma unroll
            for (int hh = 0; hh < 2; hh++) {
                int r = r0 + mi * 16 + hh * 8;
                float2 v;
                v.x = 1.0f / (1.0f + expf(acc[mi][nf][hh * 2 + 0] + b0));
                v.y = 1.0f / (1.0f + expf(acc[mi][nf][hh * 2 + 1] + b1));
                *(float2*)(op + (size_t)r * DSZ + dbase + col) = v;
            }
        }
}

// ---------------- conversion kernels -------------------------------------------
// x -> fragment-packed fp16: thread = one (band, k16, lane) 16B frag
__global__ __launch_bounds__(256) void conv_x_k(const float* __restrict__ x) {
    const size_t idx = (size_t)blockIdx.x * 256 + threadIdx.x;   // 0..2097151
    const int lane = idx & 31;
    const int k16  = ((int)(idx >> 5)) & 63;
    const int band = (int)(idx >> 11);
    const int g = lane >> 2, t = lane & 3;
    const size_t r0 = (size_t)(band * 16 + g) * DIN;
    const size_t r8 = r0 + 8 * DIN;
    const int col = k16 * 16 + 2 * t;
    float2 v00 = *(const float2*)(x + r0 + col);
    float2 v10 = *(const float2*)(x + r8 + col);
    float2 v01 = *(const float2*)(x + r0 + col + 8);
    float2 v11 = *(const float2*)(x + r8 + col + 8);
    uint4 w;
    w.x = pack_h2(v00.x, v00.y);
    w.y = pack_h2(v10.x, v10.y);
    w.z = pack_h2(v01.x, v01.y);
    w.w = pack_h2(v11.x, v11.y);
    xp_g[idx] = w;
}

__global__ void conv_w1_all_k(const float* __restrict__ Wg1,
                              const float* __restrict__ Wdr,
                              const float* __restrict__ Wdi) {
    __shared__ float t[32][33];
    int z = blockIdx.z;
    const float* base = (z < 4 ? Wg1 : (z < 8 ? Wdr : Wdi));
    const float* sp = base + (size_t)(z & 3) * DIN * DSZ;
    int tx = threadIdx.x, ty = threadIdx.y;
    int k0 = blockIdx.x * 32, d0 = blockIdx.y * 32;
#pragma unroll
    for (int i = 0; i < 4; i++)
        t[ty + i * 8][tx] = sp[(size_t)(k0 + ty + i * 8) * DSZ + d0 + tx];
    __syncthreads();
    __half* oh = w1f16_g + (size_t)z * DSZ * DIN;
#pragma unroll
    for (int i = 0; i < 4; i++) {
        int n = d0 + ty + i * 8, k = k0 + tx;
        oh[(size_t)n * DIN + k] = __float2half_rn(t[tx][ty + i * 8]);
    }
}

__global__ void conv_w2_k(const float* __restrict__ src) {
    __shared__ float t[32][33];
    int z = blockIdx.z;
    const float* sp = src + (size_t)z * DSZ * DSZ;
    int tx = threadIdx.x, ty = threadIdx.y;
    int k0 = blockIdx.x * 32, d0 = blockIdx.y * 32;
#pragma unroll
    for (int i = 0; i < 4; i++)
        t[ty + i * 8][tx] = sp[(size_t)(k0 + ty + i * 8) * DSZ + d0 + tx];
    __syncthreads();
    __half* oh = w2f16_g + (size_t)z * DSZ * DSZ;
#pragma unroll
    for (int i = 0; i < 4; i++) {
        int n = d0 + ty + i * 8, k = k0 + tx;
        oh[(size_t)n * DSZ + k] = __float2half_rn(t[tx][ty + i * 8]);
    }
}

// ---------------- segmented scan (3 phases, proven) -----------------------------
struct ScanConsts { float abr[4], abi[4], bsc[4]; };

__global__ __launch_bounds__(256) void scan_p1(ScanConsts c) {
    const int idx = blockIdx.x;
    const int seg = idx & 15, s = (idx >> 4) & 3, b = idx >> 6;
    const int d = threadIdx.x;
    const float abr = c.abr[s], abi = c.abi[s], bs = c.bsc[s];
    const size_t base = ((size_t)s * MTOT + (size_t)b * 4096 + seg * 256) * DSZ + d;
    float Ar = 1.f, Ai = 0.f, Hr = 0.f, Hi = 0.f;
#pragma unroll 4
    for (int t = 0; t < 256; t++) {
        size_t off = base + (size_t)t * DSZ;
        float w  = omg_g[off];
        float xr = __half2float(dre_g[off]);
        float xi = __half2float(dim_g[off]);
        float ar = w * abr, ai = w * abi, wb = w * bs;
        float br = wb * xr, bi = wb * xi;
        float nHr = fmaf(ar, Hr, fmaf(-ai, Hi, br));
        float nHi = fmaf(ar, Hi, fmaf( ai, Hr, bi));
        float nAr = fmaf(ar, Ar, -ai * Ai);
        float nAi = fmaf(ar, Ai,  ai * Ar);
        Hr = nHr; Hi = nHi; Ar = nAr; Ai = nAi;
    }
    Aseg_g[idx * 256 + d] = make_float2(Ar, Ai);
    Hseg_g[idx * 256 + d] = make_float2(Hr, Hi);
}

__global__ __launch_bounds__(256) void scan_p2() {
    const int bs_ = blockIdx.x;
    const int d = threadIdx.x;
    float cr = 0.f, ci = 0.f;
#pragma unroll
    for (int g = 0; g < 16; g++) {
        int idx = (bs_ * 16 + g) * 256 + d;
        Ini_g[idx] = make_float2(cr, ci);
        float2 A = Aseg_g[idx];
        float2 H = Hseg_g[idx];
        float ncr = fmaf(A.x, cr, fmaf(-A.y, ci, H.x));
        float nci = fmaf(A.x, ci, fmaf( A.y, cr, H.y));
        cr = ncr; ci = nci;
    }
}

__global__ __launch_bounds__(256) void scan_p3(float* __restrict__ out, ScanConsts c) {
    const int idx = blockIdx.x;
    const int seg = idx & 15, s = (idx >> 4) & 3, b = idx >> 6;
    const int d = threadIdx.x;
    const float abr = c.abr[s], abi = c.abi[s], bs = c.bsc[s];
    const size_t base = ((size_t)s * MTOT + (size_t)b * 4096 + seg * 256) * DSZ + d;
    float2 h0 = Ini_g[idx * 256 + d];
    float hr = h0.x, hi = h0.y;
    float* op = out + ((size_t)b * 4096 + seg * 256) * 2048 + (size_t)s * 512 + d;
#pragma unroll 4
    for (int t = 0; t < 256; t++) {
        size_t off = base + (size_t)t * DSZ;
        float w  = omg_g[off];
        float xr = __half2float(dre_g[off]);
        float xi = __half2float(dim_g[off]);
        float ar = w * abr, ai = w * abi, wb = w * bs;
        float br = wb * xr, bi = wb * xi;
        float nhr = fmaf(ar, hr, fmaf(-ai, hi, br));
        float nhi = fmaf(ar, hi, fmaf( ai, hr, bi));
        hr = nhr; hi = nhi;
        op[(size_t)t * 2048]       = hr;
        op[(size_t)t * 2048 + 256] = hi;
    }
}

// ---------------- host ----------------------------------------------------------
extern "C" void kernel_launch(void* const* d_in, const int* in_sizes, int n_in,
                              void* d_out, int out_size)
{
    const float* x   = (const float*)d_in[0];
    const float* Wg1 = (const float*)d_in[1];
    const float* bg1 = (const float*)d_in[2];
    const float* Wg2 = (const float*)d_in[3];
    const float* bg2 = (const float*)d_in[4];
    const float* Wdr = (const float*)d_in[5];
    const float* bdr = (const float*)d_in[6];
    const float* Wdi = (const float*)d_in[7];
    const float* bdi = (const float*)d_in[8];
    float* out = (float*)d_out;

    cudaFuncSetAttribute(gemm1_k, cudaFuncAttributeMaxDynamicSharedMemorySize, SMEM_SZ);
    cudaFuncSetAttribute(gemm2_k, cudaFuncAttributeMaxDynamicSharedMemorySize, SMEM_SZ);

    conv_x_k<<<8192, 256>>>(x);
    dim3 tb(32, 8);
    conv_w1_all_k<<<dim3(32, 8, 12), tb>>>(Wg1, Wdr, Wdi);
    conv_w2_k<<<dim3(8, 8, 4), tb>>>(Wg2);

    gemm1_k<<<dim3(MTOT / 128, 24), 256, SMEM_SZ>>>(bg1, bdr, bdi);
    gemm2_k<<<dim3(MTOT / 128, 8), 256, SMEM_SZ>>>(bg2);

    ScanConsts c;
    const double r [4] = {1.0, 0.999, 0.9495, 0.9};
    const double th[4] = {0.0, 0.01,  0.505,  1.0};
    for (int s = 0; s < 4; s++) {
        c.abr[s] = (float)(r[s] * cos(th[s]));
        c.abi[s] = (float)(r[s] * sin(th[s]));
        c.bsc[s] = (float)((r[s] >= 1.0) ? (1.0 / 16.0) : (1.0 - r[s]));
    }
    scan_p1<<<256, 256>>>(c);
    scan_p2<<<16, 256>>>();
    scan_p3<<<256, 256>>>(out, c);
}

// round 11
// speedup vs baseline: 1.2974x; 1.0216x over previous
#include <cuda_runtime.h>
#include <cuda_fp16.h>
#include <stdint.h>
#include <math.h>

#define MTOT 16384
#define DIN  1024
#define DSZ  256
#define KCH  64            // k-halfs per chunk
#define LDR  144           // B smem row stride (128 data + 16 pad)
#define PLB  (128 * LDR)   // 18432 bytes: one B stage (128 n-rows)
#define NST  3
#define SMEM_SZ (NST * PLB)   // 55296

// ---------------- scratch (__device__ globals; no allocations) ----------------
__device__ uint4  xp_g[(size_t)1024 * 64 * 32];      // x fragment-packed: [band][k16][lane]
__device__ __half w1f16_g[(size_t)12 * DSZ * DIN];   // [mat*4+s][n=d][k]
__device__ __half w2f16_g[(size_t)4 * DSZ * DSZ];    // [s][n=e][k]
__device__ uint4  g1p_g[(size_t)4 * 1024 * 16 * 32]; // g1 fragment-packed: [s][band][k16][lane]
__device__ __half dre_g[(size_t)4 * MTOT * DSZ];
__device__ __half dim_g[(size_t)4 * MTOT * DSZ];
__device__ float  omg_g[(size_t)4 * MTOT * DSZ];
__device__ float2 Aseg_g[256 * 256];
__device__ float2 Hseg_g[256 * 256];

// ---------------- helpers -------------------------------------------------------
__device__ __forceinline__ uint32_t pack_h2(float a, float b) {
    union { __half2 h; uint32_t u; } p;
    p.h = __halves2half2(__float2half_rn(a), __float2half_rn(b));
    return p.u;
}
__device__ __forceinline__ uint32_t smem_u32(const void* p) {
    uint32_t a;
    asm("{ .reg .u64 t; cvta.to.shared.u64 t, %1; cvt.u32.u64 %0, t; }" : "=r"(a) : "l"(p));
    return a;
}
__device__ __forceinline__ void cpa16(uint32_t dst, const void* src) {
    asm volatile("cp.async.cg.shared.global [%0], [%1], 16;" :: "r"(dst), "l"(src));
}
__device__ __forceinline__ void cpa_commit() {
    asm volatile("cp.async.commit_group;");
}
template<int N> __device__ __forceinline__ void cpa_wait() {
    asm volatile("cp.async.wait_group %0;" :: "n"(N));
}
__device__ __forceinline__ void ldsm4(uint32_t r[4], uint32_t addr) {
    asm volatile("ldmatrix.sync.aligned.m8n8.x4.shared.b16 {%0,%1,%2,%3}, [%4];"
        : "=r"(r[0]), "=r"(r[1]), "=r"(r[2]), "=r"(r[3]) : "r"(addr));
}
__device__ __forceinline__ void mma_f16u(float c[4], uint32_t a0, uint32_t a1, uint32_t a2, uint32_t a3,
                                         const uint32_t b[2]) {
    asm volatile("mma.sync.aligned.m16n8k16.row.col.f32.f16.f16.f32 "
        "{%0,%1,%2,%3}, {%4,%5,%6,%7}, {%8,%9}, {%0,%1,%2,%3};"
        : "+f"(c[0]), "+f"(c[1]), "+f"(c[2]), "+f"(c[3])
        : "r"(a0), "r"(a1), "r"(a2), "r"(a3), "r"(b[0]), "r"(b[1]));
}

// ---------------- GEMM pipeline: A fragment-direct + cross-chunk A prefetch -----
// C[128,128]; 8 warps (4m x 2n). A ks0-frags for chunk ch+1 prefetched during ch.
template<int NCH>
__device__ __forceinline__ void gemm_pipeline_ad(
    const uint4* __restrict__ pA0, const uint4* __restrict__ pA1,
    const __half* __restrict__ gB, const int ldk, uint32_t s0, uint32_t bBase,
    float acc[2][8][4])
{
    const int tid = threadIdx.x;

    auto issueB = [&](int st, int k0) {
        uint32_t base = s0 + st * PLB;
#pragma unroll
        for (int it = 0; it < 4; it++) {
            int q = tid + it * 256;
            int r = q >> 3, c = q & 7;
            cpa16(base + r * LDR + c * 16, gB + (size_t)r * ldk + k0 + c * 8);
        }
        cpa_commit();
    };

#pragma unroll
    for (int i = 0; i < 2; i++)
#pragma unroll
        for (int j = 0; j < 8; j++)
#pragma unroll
            for (int k = 0; k < 4; k++) acc[i][j][k] = 0.f;

    issueB(0, 0);
    if (NCH > 1) issueB(1, KCH);

    uint4 a0n = pA0[0];           // chunk0 ks0 frags (in flight before loop)
    uint4 a1n = pA1[0];

    int st = 0;
    for (int ch = 0; ch < NCH; ch++) {
        if (ch >= NCH - 1) cpa_wait<0>(); else cpa_wait<1>();
        __syncthreads();
        if (ch + 2 < NCH) {
            int st2 = st + 2; if (st2 >= 3) st2 -= 3;
            issueB(st2, (ch + 2) * KCH);
        }
        const uint4 a0c = a0n, a1c = a1n;
        if (ch + 1 < NCH) {       // prefetch next chunk's ks0 frags now (hides L2 lat)
            a0n = pA0[(size_t)(ch + 1) * 4 * 32];
            a1n = pA1[(size_t)(ch + 1) * 4 * 32];
        }
        const uint32_t sb = s0 + st * PLB;
#pragma unroll
        for (int ks = 0; ks < 4; ks++) {
            const int k16 = ch * 4 + ks;
            uint4 a0 = (ks == 0) ? a0c : pA0[(size_t)k16 * 32];
            uint4 a1 = (ks == 0) ? a1c : pA1[(size_t)k16 * 32];
            uint32_t bb[4][4];
#pragma unroll
            for (int nf4 = 0; nf4 < 4; nf4++)
                ldsm4(bb[nf4], sb + bBase + nf4 * (16 * LDR) + ks * 32);
#pragma unroll
            for (int nf = 0; nf < 8; nf++) {
                const uint32_t* bp = &bb[nf >> 1][(nf & 1) * 2];
                mma_f16u(acc[0][nf], a0.x, a0.y, a0.z, a0.w, bp);
                mma_f16u(acc[1][nf], a1.x, a1.y, a1.z, a1.w, bp);
            }
        }
        if (++st >= 3) st = 0;
    }
}

// ---------------- GEMM 1: x @ {Wg1,Wdr,Wdi} -----------------------------------
__global__ __launch_bounds__(256, 2) void gemm1_k(
    const float* __restrict__ bg1, const float* __restrict__ bdr, const float* __restrict__ bdi)
{
    extern __shared__ char sm[];
    uint32_t s0 = smem_u32(sm);

    const int mbase = blockIdx.x * 128;
    const int nb = blockIdx.y;                 // 0..23
    const int mat = nb >> 3;
    const int s = (nb >> 1) & 3;
    const int dbase = (nb & 1) * 128;

    const int lane = threadIdx.x & 31, warp = threadIdx.x >> 5;
    const int wm = warp & 3, wn = warp >> 2;
    const int band0 = (mbase >> 4) + wm * 2;

    const uint4* pA0 = xp_g + ((size_t)band0 * 64) * 32 + lane;
    const uint4* pA1 = xp_g + ((size_t)(band0 + 1) * 64) * 32 + lane;
    const __half* gB = w1f16_g + ((size_t)(mat * 4 + s) * DSZ + dbase) * DIN;
    const uint32_t bBase = (uint32_t)(wn * 64 + (lane & 7) + ((lane & 16) >> 1)) * LDR
                         + ((lane >> 3) & 1) * 16;

    float acc[2][8][4];
    gemm_pipeline_ad<DIN / KCH>(pA0, pA1, gB, DIN, s0, bBase, acc);

    const int c0 = wn * 64 + (lane & 3) * 2;
    const float* bias = (mat == 0 ? bg1 : (mat == 1 ? bdr : bdi)) + s * DSZ + dbase;

    if (mat == 0) {
        uint4* gp = g1p_g + ((size_t)s * 1024 * 16) * 32;
#pragma unroll
        for (int mi = 0; mi < 2; mi++) {
            const int band = band0 + mi;
#pragma unroll
            for (int p = 0; p < 4; p++) {
                const int nf = 2 * p;
                const int col = c0 + nf * 8;
                float b0 = bias[col],      b1 = bias[col + 1];
                float b2 = bias[col + 8],  b3 = bias[col + 9];
                uint4 w;
                w.x = pack_h2(fmaxf(acc[mi][nf][0] + b0, 0.f),
                              fmaxf(acc[mi][nf][1] + b1, 0.f));
                w.y = pack_h2(fmaxf(acc[mi][nf][2] + b0, 0.f),
                              fmaxf(acc[mi][nf][3] + b1, 0.f));
                w.z = pack_h2(fmaxf(acc[mi][nf + 1][0] + b2, 0.f),
                              fmaxf(acc[mi][nf + 1][1] + b3, 0.f));
                w.w = pack_h2(fmaxf(acc[mi][nf + 1][2] + b2, 0.f),
                              fmaxf(acc[mi][nf + 1][3] + b3, 0.f));
                const int k16 = (dbase + wn * 64 + nf * 8) >> 4;
                gp[((size_t)band * 16 + k16) * 32 + lane] = w;
            }
        }
    } else {
        const int r0 = mbase + wm * 32 + (lane >> 2);
        __half* op = (mat == 1 ? dre_g : dim_g) + (size_t)s * MTOT * DSZ;
#pragma unroll
        for (int mi = 0; mi < 2; mi++)
#pragma unroll
            for (int nf = 0; nf < 8; nf++) {
                int col = c0 + nf * 8;
                float b0 = bias[col], b1 = bias[col + 1];
#pragma unroll
                for (int hh = 0; hh < 2; hh++) {
                    int r = r0 + mi * 16 + hh * 8;
                    union { __half2 h; uint32_t u; } pk;
                    pk.u = pack_h2(acc[mi][nf][hh * 2 + 0] + b0,
                                   acc[mi][nf][hh * 2 + 1] + b1);
                    *(__half2*)(op + (size_t)r * DSZ + dbase + col) = pk.h;
                }
            }
    }
}

// ---------------- GEMM 2: omg = 1 - sigmoid(g1 @ Wg2 + bg2) --------------------
__global__ __launch_bounds__(256, 2) void gemm2_k(const float* __restrict__ bg2)
{
    extern __shared__ char sm[];
    uint32_t s0 = smem_u32(sm);

    const int mbase = blockIdx.x * 128;
    const int s = blockIdx.y >> 1;
    const int dbase = (blockIdx.y & 1) * 128;

    const int lane = threadIdx.x & 31, warp = threadIdx.x >> 5;
    const int wm = warp & 3, wn = warp >> 2;
    const int band0 = (mbase >> 4) + wm * 2;

    const uint4* pA0 = g1p_g + ((size_t)(s * 1024 + band0) * 16) * 32 + lane;
    const uint4* pA1 = g1p_g + ((size_t)(s * 1024 + band0 + 1) * 16) * 32 + lane;
    const __half* gB = w2f16_g + ((size_t)s * DSZ + dbase) * DSZ;
    const uint32_t bBase = (uint32_t)(wn * 64 + (lane & 7) + ((lane & 16) >> 1)) * LDR
                         + ((lane >> 3) & 1) * 16;

    float acc[2][8][4];
    gemm_pipeline_ad<DSZ / KCH>(pA0, pA1, gB, DSZ, s0, bBase, acc);

    const int r0 = mbase + wm * 32 + (lane >> 2);
    const int c0 = wn * 64 + (lane & 3) * 2;
    const float* bias = bg2 + s * DSZ + dbase;
    float* op = omg_g + (size_t)s * MTOT * DSZ;

#pragma unroll
    for (int mi = 0; mi < 2; mi++)
#pragma unroll
        for (int nf = 0; nf < 8; nf++) {
            int col = c0 + nf * 8;
            float b0 = bias[col], b1 = bias[col + 1];
#pragma unroll
            for (int hh = 0; hh < 2; hh++) {
                int r = r0 + mi * 16 + hh * 8;
                float2 v;
                v.x = 1.0f / (1.0f + expf(acc[mi][nf][hh * 2 + 0] + b0));
                v.y = 1.0f / (1.0f + expf(acc[mi][nf][hh * 2 + 1] + b1));
                *(float2*)(op + (size_t)r * DSZ + dbase + col) = v;
            }
        }
}

// ---------------- conversion kernels -------------------------------------------
__global__ __launch_bounds__(256) void conv_x_k(const float* __restrict__ x) {
    const size_t idx = (size_t)blockIdx.x * 256 + threadIdx.x;
    const int lane = idx & 31;
    const int k16  = ((int)(idx >> 5)) & 63;
    const int band = (int)(idx >> 11);
    const int g = lane >> 2, t = lane & 3;
    const size_t r0 = (size_t)(band * 16 + g) * DIN;
    const size_t r8 = r0 + 8 * DIN;
    const int col = k16 * 16 + 2 * t;
    float2 v00 = *(const float2*)(x + r0 + col);
    float2 v10 = *(const float2*)(x + r8 + col);
    float2 v01 = *(const float2*)(x + r0 + col + 8);
    float2 v11 = *(const float2*)(x + r8 + col + 8);
    uint4 w;
    w.x = pack_h2(v00.x, v00.y);
    w.y = pack_h2(v10.x, v10.y);
    w.z = pack_h2(v01.x, v01.y);
    w.w = pack_h2(v11.x, v11.y);
    xp_g[idx] = w;
}

// all W1 (z 0..11) + W2 (z 12..15) in one launch
__global__ void conv_w_all_k(const float* __restrict__ Wg1,
                             const float* __restrict__ Wdr,
                             const float* __restrict__ Wdi,
                             const float* __restrict__ Wg2) {
    __shared__ float t[32][33];
    int z = blockIdx.z;
    const int kdim = (z < 12) ? DIN : DSZ;
    if (blockIdx.x * 32 >= kdim) return;
    const float* base = (z < 4 ? Wg1 : (z < 8 ? Wdr : (z < 12 ? Wdi : Wg2)));
    const float* sp = base + (size_t)(z & 3) * kdim * DSZ;
    int tx = threadIdx.x, ty = threadIdx.y;
    int k0 = blockIdx.x * 32, d0 = blockIdx.y * 32;
#pragma unroll
    for (int i = 0; i < 4; i++)
        t[ty + i * 8][tx] = sp[(size_t)(k0 + ty + i * 8) * DSZ + d0 + tx];
    __syncthreads();
    __half* oh = (z < 12) ? (w1f16_g + (size_t)z * DSZ * DIN)
                          : (w2f16_g + (size_t)(z - 12) * DSZ * DSZ);
#pragma unroll
    for (int i = 0; i < 4; i++) {
        int n = d0 + ty + i * 8, k = k0 + tx;
        oh[(size_t)n * kdim + k] = __float2half_rn(t[tx][ty + i * 8]);
    }
}

// ---------------- segmented scan (2 phases; p3 folds its own prefix) ------------
struct ScanConsts { float abr[4], abi[4], bsc[4]; };

__global__ __launch_bounds__(256) void scan_p1(ScanConsts c) {
    const int idx = blockIdx.x;
    const int seg = idx & 15, s = (idx >> 4) & 3, b = idx >> 6;
    const int d = threadIdx.x;
    const float abr = c.abr[s], abi = c.abi[s], bs = c.bsc[s];
    const size_t base = ((size_t)s * MTOT + (size_t)b * 4096 + seg * 256) * DSZ + d;
    float Ar = 1.f, Ai = 0.f, Hr = 0.f, Hi = 0.f;
#pragma unroll 4
    for (int t = 0; t < 256; t++) {
        size_t off = base + (size_t)t * DSZ;
        float w  = omg_g[off];
        float xr = __half2float(dre_g[off]);
        float xi = __half2float(dim_g[off]);
        float ar = w * abr, ai = w * abi, wb = w * bs;
        float br = wb * xr, bi = wb * xi;
        float nHr = fmaf(ar, Hr, fmaf(-ai, Hi, br));
        float nHi = fmaf(ar, Hi, fmaf( ai, Hr, bi));
        float nAr = fmaf(ar, Ar, -ai * Ai);
        float nAi = fmaf(ar, Ai,  ai * Ar);
        Hr = nHr; Hi = nHi; Ar = nAr; Ai = nAi;
    }
    Aseg_g[idx * 256 + d] = make_float2(Ar, Ai);
    Hseg_g[idx * 256 + d] = make_float2(Hr, Hi);
}

__global__ __launch_bounds__(256) void scan_p3(float* __restrict__ out, ScanConsts c) {
    const int idx = blockIdx.x;
    const int seg = idx & 15, s = (idx >> 4) & 3, b = idx >> 6;
    const int d = threadIdx.x;
    const float abr = c.abr[s], abi = c.abi[s], bs = c.bsc[s];
    const size_t base = ((size_t)s * MTOT + (size_t)b * 4096 + seg * 256) * DSZ + d;

    // fold predecessor aggregates (same op order as former scan_p2)
    float hr = 0.f, hi = 0.f;
    const int rowbase = idx - seg;
    for (int g = 0; g < seg; g++) {
        float2 A = Aseg_g[(rowbase + g) * 256 + d];
        float2 H = Hseg_g[(rowbase + g) * 256 + d];
        float nhr = fmaf(A.x, hr, fmaf(-A.y, hi, H.x));
        float nhi = fmaf(A.x, hi, fmaf( A.y, hr, H.y));
        hr = nhr; hi = nhi;
    }

    float* op = out + ((size_t)b * 4096 + seg * 256) * 2048 + (size_t)s * 512 + d;
#pragma unroll 4
    for (int t = 0; t < 256; t++) {
        size_t off = base + (size_t)t * DSZ;
        float w  = omg_g[off];
        float xr = __half2float(dre_g[off]);
        float xi = __half2float(dim_g[off]);
        float ar = w * abr, ai = w * abi, wb = w * bs;
        float br = wb * xr, bi = wb * xi;
        float nhr = fmaf(ar, hr, fmaf(-ai, hi, br));
        float nhi = fmaf(ar, hi, fmaf( ai, hr, bi));
        hr = nhr; hi = nhi;
        op[(size_t)t * 2048]       = hr;
        op[(size_t)t * 2048 + 256] = hi;
    }
}

// ---------------- host ----------------------------------------------------------
extern "C" void kernel_launch(void* const* d_in, const int* in_sizes, int n_in,
                              void* d_out, int out_size)
{
    const float* x   = (const float*)d_in[0];
    const float* Wg1 = (const float*)d_in[1];
    const float* bg1 = (const float*)d_in[2];
    const float* Wg2 = (const float*)d_in[3];
    const float* bg2 = (const float*)d_in[4];
    const float* Wdr = (const float*)d_in[5];
    const float* bdr = (const float*)d_in[6];
    const float* Wdi = (const float*)d_in[7];
    const float* bdi = (const float*)d_in[8];
    float* out = (float*)d_out;

    cudaFuncSetAttribute(gemm1_k, cudaFuncAttributeMaxDynamicSharedMemorySize, SMEM_SZ);
    cudaFuncSetAttribute(gemm2_k, cudaFuncAttributeMaxDynamicSharedMemorySize, SMEM_SZ);

    conv_x_k<<<8192, 256>>>(x);
    dim3 tb(32, 8);
    conv_w_all_k<<<dim3(32, 8, 16), tb>>>(Wg1, Wdr, Wdi, Wg2);

    gemm1_k<<<dim3(MTOT / 128, 24), 256, SMEM_SZ>>>(bg1, bdr, bdi);
    gemm2_k<<<dim3(MTOT / 128, 8), 256, SMEM_SZ>>>(bg2);

    ScanConsts c;
    const double r [4] = {1.0, 0.999, 0.9495, 0.9};
    const double th[4] = {0.0, 0.01,  0.505,  1.0};
    for (int s = 0; s < 4; s++) {
        c.abr[s] = (float)(r[s] * cos(th[s]));
        c.abi[s] = (float)(r[s] * sin(th[s]));
        c.bsc[s] = (float)((r[s] >= 1.0) ? (1.0 / 16.0) : (1.0 - r[s]));
    }
    scan_p1<<<256, 256>>>(c);
    scan_p3<<<256, 256>>>(out, c);
}

// round 12
// speedup vs baseline: 1.3253x; 1.0215x over previous
#include <cuda_runtime.h>
#include <cuda_fp16.h>
#include <stdint.h>
#include <math.h>

#define MTOT 16384
#define DIN  1024
#define DSZ  256

// gemm1: KCH=128 halfs (256B/row), 3-stage
#define KCH1  128
#define LDR1  272
#define PLB1  (128 * LDR1)       // 34816
#define NST1  3
#define SMEM1 (NST1 * PLB1)      // 104448 -> 2 CTAs/SM
// gemm2: whole-K B resident (512B/row)
#define LDR2  528
#define SMEM2 (128 * LDR2)       // 67584 -> 2 CTAs/SM

// ---------------- scratch (__device__ globals; no allocations) ----------------
__device__ uint4  xp_g[(size_t)1024 * 64 * 32];      // x frag-packed: [band][k16][lane]
__device__ __half w1f16_g[(size_t)12 * DSZ * DIN];   // [mat*4+s][n=d][k]
__device__ __half w2f16_g[(size_t)4 * DSZ * DSZ];    // [s][n=e][k]
__device__ uint4  g1p_g[(size_t)4 * 1024 * 16 * 32]; // g1 frag-packed: [s][band][k16][lane]
__device__ __half dre_g[(size_t)4 * MTOT * DSZ];
__device__ __half dim_g[(size_t)4 * MTOT * DSZ];
__device__ float  omg_g[(size_t)4 * MTOT * DSZ];
__device__ float2 Aseg_g[256 * 256];
__device__ float2 Hseg_g[256 * 256];

// ---------------- helpers -------------------------------------------------------
__device__ __forceinline__ uint32_t pack_h2(float a, float b) {
    union { __half2 h; uint32_t u; } p;
    p.h = __halves2half2(__float2half_rn(a), __float2half_rn(b));
    return p.u;
}
__device__ __forceinline__ uint32_t smem_u32(const void* p) {
    uint32_t a;
    asm("{ .reg .u64 t; cvta.to.shared.u64 t, %1; cvt.u32.u64 %0, t; }" : "=r"(a) : "l"(p));
    return a;
}
__device__ __forceinline__ void cpa16(uint32_t dst, const void* src) {
    asm volatile("cp.async.cg.shared.global [%0], [%1], 16;" :: "r"(dst), "l"(src));
}
__device__ __forceinline__ void cpa_commit() {
    asm volatile("cp.async.commit_group;");
}
template<int N> __device__ __forceinline__ void cpa_wait() {
    asm volatile("cp.async.wait_group %0;" :: "n"(N));
}
__device__ __forceinline__ void ldsm4(uint32_t r[4], uint32_t addr) {
    asm volatile("ldmatrix.sync.aligned.m8n8.x4.shared.b16 {%0,%1,%2,%3}, [%4];"
        : "=r"(r[0]), "=r"(r[1]), "=r"(r[2]), "=r"(r[3]) : "r"(addr));
}
__device__ __forceinline__ void mma_f16u(float c[4], uint32_t a0, uint32_t a1, uint32_t a2, uint32_t a3,
                                         const uint32_t b[2]) {
    asm volatile("mma.sync.aligned.m16n8k16.row.col.f32.f16.f16.f32 "
        "{%0,%1,%2,%3}, {%4,%5,%6,%7}, {%8,%9}, {%0,%1,%2,%3};"
        : "+f"(c[0]), "+f"(c[1]), "+f"(c[2]), "+f"(c[3])
        : "r"(a0), "r"(a1), "r"(a2), "r"(a3), "r"(b[0]), "r"(b[1]));
}

// ---------------- GEMM 1: x @ {Wg1,Wdr,Wdi}; A frag-direct, B smem KCH=128 ------
__global__ __launch_bounds__(256, 2) void gemm1_k(
    const float* __restrict__ bg1, const float* __restrict__ bdr, const float* __restrict__ bdi)
{
    extern __shared__ char sm[];
    uint32_t s0 = smem_u32(sm);
    const int tid = threadIdx.x;

    const int mbase = blockIdx.x * 128;
    const int nb = blockIdx.y;                 // 0..23
    const int mat = nb >> 3;
    const int s = (nb >> 1) & 3;
    const int dbase = (nb & 1) * 128;

    const int lane = tid & 31, warp = tid >> 5;
    const int wm = warp & 3, wn = warp >> 2;
    const int band0 = (mbase >> 4) + wm * 2;

    const uint4* pA0 = xp_g + ((size_t)band0 * 64) * 32 + lane;
    const uint4* pA1 = xp_g + ((size_t)(band0 + 1) * 64) * 32 + lane;
    const __half* gB = w1f16_g + ((size_t)(mat * 4 + s) * DSZ + dbase) * DIN;
    const uint32_t bBase = (uint32_t)(wn * 64 + (lane & 7) + ((lane & 16) >> 1)) * LDR1
                         + ((lane >> 3) & 1) * 16;

    auto issueB = [&](int st, int k0) {
        uint32_t base = s0 + st * PLB1;
#pragma unroll
        for (int it = 0; it < 8; it++) {
            int q = tid + it * 256;
            int r = q >> 4, c = q & 15;
            cpa16(base + r * LDR1 + c * 16, gB + (size_t)r * DIN + k0 + c * 8);
        }
        cpa_commit();
    };

    float acc[2][8][4];
#pragma unroll
    for (int i = 0; i < 2; i++)
#pragma unroll
        for (int j = 0; j < 8; j++)
#pragma unroll
            for (int k = 0; k < 4; k++) acc[i][j][k] = 0.f;

    constexpr int NCH = DIN / KCH1;    // 8
    issueB(0, 0);
    issueB(1, KCH1);

    uint4 a0n = pA0[0];
    uint4 a1n = pA1[0];

    int st = 0;
    for (int ch = 0; ch < NCH; ch++) {
        if (ch >= NCH - 1) cpa_wait<0>(); else cpa_wait<1>();
        __syncthreads();
        if (ch + 2 < NCH) {
            int st2 = st + 2; if (st2 >= 3) st2 -= 3;
            issueB(st2, (ch + 2) * KCH1);
        }
        const uint4 a0c = a0n, a1c = a1n;
        if (ch + 1 < NCH) {
            a0n = pA0[(size_t)(ch + 1) * 8 * 32];
            a1n = pA1[(size_t)(ch + 1) * 8 * 32];
        }
        const uint32_t sb = s0 + st * PLB1;
#pragma unroll
        for (int ks = 0; ks < 8; ks++) {
            const int k16 = ch * 8 + ks;
            uint4 a0 = (ks == 0) ? a0c : pA0[(size_t)k16 * 32];
            uint4 a1 = (ks == 0) ? a1c : pA1[(size_t)k16 * 32];
            uint32_t bb[4][4];
#pragma unroll
            for (int nf4 = 0; nf4 < 4; nf4++)
                ldsm4(bb[nf4], sb + bBase + nf4 * (16 * LDR1) + ks * 32);
#pragma unroll
            for (int nf = 0; nf < 8; nf++) {
                const uint32_t* bp = &bb[nf >> 1][(nf & 1) * 2];
                mma_f16u(acc[0][nf], a0.x, a0.y, a0.z, a0.w, bp);
                mma_f16u(acc[1][nf], a1.x, a1.y, a1.z, a1.w, bp);
            }
        }
        if (++st >= 3) st = 0;
    }

    const int c0 = wn * 64 + (lane & 3) * 2;
    const float* bias = (mat == 0 ? bg1 : (mat == 1 ? bdr : bdi)) + s * DSZ + dbase;

    if (mat == 0) {
        uint4* gp = g1p_g + ((size_t)s * 1024 * 16) * 32;
#pragma unroll
        for (int mi = 0; mi < 2; mi++) {
            const int band = band0 + mi;
#pragma unroll
            for (int p = 0; p < 4; p++) {
                const int nf = 2 * p;
                const int col = c0 + nf * 8;
                float b0 = bias[col],      b1 = bias[col + 1];
                float b2 = bias[col + 8],  b3 = bias[col + 9];
                uint4 w;
                w.x = pack_h2(fmaxf(acc[mi][nf][0] + b0, 0.f),
                              fmaxf(acc[mi][nf][1] + b1, 0.f));
                w.y = pack_h2(fmaxf(acc[mi][nf][2] + b0, 0.f),
                              fmaxf(acc[mi][nf][3] + b1, 0.f));
                w.z = pack_h2(fmaxf(acc[mi][nf + 1][0] + b2, 0.f),
                              fmaxf(acc[mi][nf + 1][1] + b3, 0.f));
                w.w = pack_h2(fmaxf(acc[mi][nf + 1][2] + b2, 0.f),
                              fmaxf(acc[mi][nf + 1][3] + b3, 0.f));
                const int k16 = (dbase + wn * 64 + nf * 8) >> 4;
                gp[((size_t)band * 16 + k16) * 32 + lane] = w;
            }
        }
    } else {
        const int r0 = mbase + wm * 32 + (lane >> 2);
        __half* op = (mat == 1 ? dre_g : dim_g) + (size_t)s * MTOT * DSZ;
#pragma unroll
        for (int mi = 0; mi < 2; mi++)
#pragma unroll
            for (int nf = 0; nf < 8; nf++) {
                int col = c0 + nf * 8;
                float b0 = bias[col], b1 = bias[col + 1];
#pragma unroll
                for (int hh = 0; hh < 2; hh++) {
                    int r = r0 + mi * 16 + hh * 8;
                    union { __half2 h; uint32_t u; } pk;
                    pk.u = pack_h2(acc[mi][nf][hh * 2 + 0] + b0,
                                   acc[mi][nf][hh * 2 + 1] + b1);
                    *(__half2*)(op + (size_t)r * DSZ + dbase + col) = pk.h;
                }
            }
    }
}

// ---------------- GEMM 2: whole-K B resident, zero inner barriers ---------------
__global__ __launch_bounds__(256, 2) void gemm2_k(const float* __restrict__ bg2)
{
    extern __shared__ char sm[];
    uint32_t s0 = smem_u32(sm);
    const int tid = threadIdx.x;

    const int mbase = blockIdx.x * 128;
    const int s = blockIdx.y >> 1;
    const int dbase = (blockIdx.y & 1) * 128;

    const int lane = tid & 31, warp = tid >> 5;
    const int wm = warp & 3, wn = warp >> 2;
    const int band0 = (mbase >> 4) + wm * 2;

    const uint4* pA0 = g1p_g + ((size_t)(s * 1024 + band0) * 16) * 32 + lane;
    const uint4* pA1 = g1p_g + ((size_t)(s * 1024 + band0 + 1) * 16) * 32 + lane;
    const __half* gB = w2f16_g + ((size_t)s * DSZ + dbase) * DSZ;

    // single-shot load of entire B tile [128 n-rows x 256 k-halfs]
    {
#pragma unroll
        for (int it = 0; it < 16; it++) {
            int q = tid + it * 256;
            int r = q >> 5, c = q & 31;
            cpa16(s0 + r * LDR2 + c * 16, gB + (size_t)r * DSZ + c * 8);
        }
        cpa_commit();
    }

    float acc[2][8][4];
#pragma unroll
    for (int i = 0; i < 2; i++)
#pragma unroll
        for (int j = 0; j < 8; j++)
#pragma unroll
            for (int k = 0; k < 4; k++) acc[i][j][k] = 0.f;

    const uint32_t bBase = (uint32_t)(wn * 64 + (lane & 7) + ((lane & 16) >> 1)) * LDR2
                         + ((lane >> 3) & 1) * 16;

    cpa_wait<0>();
    __syncthreads();

#pragma unroll
    for (int k16 = 0; k16 < 16; k16++) {
        uint4 a0 = pA0[(size_t)k16 * 32];
        uint4 a1 = pA1[(size_t)k16 * 32];
        uint32_t bb[4][4];
#pragma unroll
        for (int nf4 = 0; nf4 < 4; nf4++)
            ldsm4(bb[nf4], s0 + bBase + nf4 * (16 * LDR2) + k16 * 32);
#pragma unroll
        for (int nf = 0; nf < 8; nf++) {
            const uint32_t* bp = &bb[nf >> 1][(nf & 1) * 2];
            mma_f16u(acc[0][nf], a0.x, a0.y, a0.z, a0.w, bp);
            mma_f16u(acc[1][nf], a1.x, a1.y, a1.z, a1.w, bp);
        }
    }

    const int r0 = mbase + wm * 32 + (lane >> 2);
    const int c0 = wn * 64 + (lane & 3) * 2;
    const float* bias = bg2 + s * DSZ + dbase;
    float* op = omg_g + (size_t)s * MTOT * DSZ;

#pragma unroll
    for (int mi = 0; mi < 2; mi++)
#pragma unroll
        for (int nf = 0; nf < 8; nf++) {
            int col = c0 + nf * 8;
            float b0 = bias[col], b1 = bias[col + 1];
#pragma unroll
            for (int hh = 0; hh < 2; hh++) {
                int r = r0 + mi * 16 + hh * 8;
                float2 v;
                v.x = 1.0f / (1.0f + expf(acc[mi][nf][hh * 2 + 0] + b0));
                v.y = 1.0f / (1.0f + expf(acc[mi][nf][hh * 2 + 1] + b1));
                *(float2*)(op + (size_t)r * DSZ + dbase + col) = v;
            }
        }
}

// ---------------- conversion kernels -------------------------------------------
__global__ __launch_bounds__(256) void conv_x_k(const float* __restrict__ x) {
    const size_t idx = (size_t)blockIdx.x * 256 + threadIdx.x;
    const int lane = idx & 31;
    const int k16  = ((int)(idx >> 5)) & 63;
    const int band = (int)(idx >> 11);
    const int g = lane >> 2, t = lane & 3;
    const size_t r0 = (size_t)(band * 16 + g) * DIN;
    const size_t r8 = r0 + 8 * DIN;
    const int col = k16 * 16 + 2 * t;
    float2 v00 = *(const float2*)(x + r0 + col);
    float2 v10 = *(const float2*)(x + r8 + col);
    float2 v01 = *(const float2*)(x + r0 + col + 8);
    float2 v11 = *(const float2*)(x + r8 + col + 8);
    uint4 w;
    w.x = pack_h2(v00.x, v00.y);
    w.y = pack_h2(v10.x, v10.y);
    w.z = pack_h2(v01.x, v01.y);
    w.w = pack_h2(v11.x, v11.y);
    xp_g[idx] = w;
}

__global__ void conv_w_all_k(const float* __restrict__ Wg1,
                             const float* __restrict__ Wdr,
                             const float* __restrict__ Wdi,
                             const float* __restrict__ Wg2) {
    __shared__ float t[32][33];
    int z = blockIdx.z;
    const int kdim = (z < 12) ? DIN : DSZ;
    if (blockIdx.x * 32 >= kdim) return;
    const float* base = (z < 4 ? Wg1 : (z < 8 ? Wdr : (z < 12 ? Wdi : Wg2)));
    const float* sp = base + (size_t)(z & 3) * kdim * DSZ;
    int tx = threadIdx.x, ty = threadIdx.y;
    int k0 = blockIdx.x * 32, d0 = blockIdx.y * 32;
#pragma unroll
    for (int i = 0; i < 4; i++)
        t[ty + i * 8][tx] = sp[(size_t)(k0 + ty + i * 8) * DSZ + d0 + tx];
    __syncthreads();
    __half* oh = (z < 12) ? (w1f16_g + (size_t)z * DSZ * DIN)
                          : (w2f16_g + (size_t)(z - 12) * DSZ * DSZ);
#pragma unroll
    for (int i = 0; i < 4; i++) {
        int n = d0 + ty + i * 8, k = k0 + tx;
        oh[(size_t)n * kdim + k] = __float2half_rn(t[tx][ty + i * 8]);
    }
}

// ---------------- segmented scan (2 phases) -------------------------------------
struct ScanConsts { float abr[4], abi[4], bsc[4]; };

__global__ __launch_bounds__(256) void scan_p1(ScanConsts c) {
    const int idx = blockIdx.x;
    const int seg = idx & 15, s = (idx >> 4) & 3, b = idx >> 6;
    const int d = threadIdx.x;
    const float abr = c.abr[s], abi = c.abi[s], bs = c.bsc[s];
    const size_t base = ((size_t)s * MTOT + (size_t)b * 4096 + seg * 256) * DSZ + d;
    float Ar = 1.f, Ai = 0.f, Hr = 0.f, Hi = 0.f;
#pragma unroll 4
    for (int t = 0; t < 256; t++) {
        size_t off = base + (size_t)t * DSZ;
        float w  = omg_g[off];
        float xr = __half2float(dre_g[off]);
        float xi = __half2float(dim_g[off]);
        float ar = w * abr, ai = w * abi, wb = w * bs;
        float br = wb * xr, bi = wb * xi;
        float nHr = fmaf(ar, Hr, fmaf(-ai, Hi, br));
        float nHi = fmaf(ar, Hi, fmaf( ai, Hr, bi));
        float nAr = fmaf(ar, Ar, -ai * Ai);
        float nAi = fmaf(ar, Ai,  ai * Ar);
        Hr = nHr; Hi = nHi; Ar = nAr; Ai = nAi;
    }
    Aseg_g[idx * 256 + d] = make_float2(Ar, Ai);
    Hseg_g[idx * 256 + d] = make_float2(Hr, Hi);
}

__global__ __launch_bounds__(256) void scan_p3(float* __restrict__ out, ScanConsts c) {
    const int idx = blockIdx.x;
    const int seg = idx & 15, s = (idx >> 4) & 3, b = idx >> 6;
    const int d = threadIdx.x;
    const float abr = c.abr[s], abi = c.abi[s], bs = c.bsc[s];
    const size_t base = ((size_t)s * MTOT + (size_t)b * 4096 + seg * 256) * DSZ + d;

    float hr = 0.f, hi = 0.f;
    const int rowbase = idx - seg;
    for (int g = 0; g < seg; g++) {
        float2 A = Aseg_g[(rowbase + g) * 256 + d];
        float2 H = Hseg_g[(rowbase + g) * 256 + d];
        float nhr = fmaf(A.x, hr, fmaf(-A.y, hi, H.x));
        float nhi = fmaf(A.x, hi, fmaf( A.y, hr, H.y));
        hr = nhr; hi = nhi;
    }

    float* op = out + ((size_t)b * 4096 + seg * 256) * 2048 + (size_t)s * 512 + d;
#pragma unroll 4
    for (int t = 0; t < 256; t++) {
        size_t off = base + (size_t)t * DSZ;
        float w  = omg_g[off];
        float xr = __half2float(dre_g[off]);
        float xi = __half2float(dim_g[off]);
        float ar = w * abr, ai = w * abi, wb = w * bs;
        float br = wb * xr, bi = wb * xi;
        float nhr = fmaf(ar, hr, fmaf(-ai, hi, br));
        float nhi = fmaf(ar, hi, fmaf( ai, hr, bi));
        hr = nhr; hi = nhi;
        op[(size_t)t * 2048]       = hr;
        op[(size_t)t * 2048 + 256] = hi;
    }
}

// ---------------- host ----------------------------------------------------------
extern "C" void kernel_launch(void* const* d_in, const int* in_sizes, int n_in,
                              void* d_out, int out_size)
{
    const float* x   = (const float*)d_in[0];
    const float* Wg1 = (const float*)d_in[1];
    const float* bg1 = (const float*)d_in[2];
    const float* Wg2 = (const float*)d_in[3];
    const float* bg2 = (const float*)d_in[4];
    const float* Wdr = (const float*)d_in[5];
    const float* bdr = (const float*)d_in[6];
    const float* Wdi = (const float*)d_in[7];
    const float* bdi = (const float*)d_in[8];
    float* out = (float*)d_out;

    cudaFuncSetAttribute(gemm1_k, cudaFuncAttributeMaxDynamicSharedMemorySize, SMEM1);
    cudaFuncSetAttribute(gemm2_k, cudaFuncAttributeMaxDynamicSharedMemorySize, SMEM2);

    conv_x_k<<<8192, 256>>>(x);
    dim3 tb(32, 8);
    conv_w_all_k<<<dim3(32, 8, 16), tb>>>(Wg1, Wdr, Wdi, Wg2);

    gemm1_k<<<dim3(MTOT / 128, 24), 256, SMEM1>>>(bg1, bdr, bdi);
    gemm2_k<<<dim3(MTOT / 128, 8), 256, SMEM2>>>(bg2);

    ScanConsts c;
    const double r [4] = {1.0, 0.999, 0.9495, 0.9};
    const double th[4] = {0.0, 0.01,  0.505,  1.0};
    for (int s = 0; s < 4; s++) {
        c.abr[s] = (float)(r[s] * cos(th[s]));
        c.abi[s] = (float)(r[s] * sin(th[s]));
        c.bsc[s] = (float)((r[s] >= 1.0) ? (1.0 / 16.0) : (1.0 - r[s]));
    }
    scan_p1<<<256, 256>>>(c);
    scan_p3<<<256, 256>>>(out, c);
}

// round 13
// speedup vs baseline: 1.4716x; 1.1104x over previous
#include <cuda_runtime.h>
#include <cuda_fp16.h>
#include <stdint.h>
#include <math.h>

#define MTOT 16384
#define DIN  1024
#define DSZ  256

// gemm1: KCH=128 halfs (256B/row), 3-stage
#define KCH1  128
#define LDR1  272
#define PLB1  (128 * LDR1)       // 34816
#define NST1  3
#define SMEM1 (NST1 * PLB1)      // 104448 -> 2 CTAs/SM
// gemm2: whole-K B resident (512B/row)
#define LDR2  528
#define SMEM2 (128 * LDR2)       // 67584 -> 2 CTAs/SM

// scan segmentation
#define NSEG 32
#define TSEG 128                 // 4096 / 32

// ---------------- scratch (__device__ globals; no allocations) ----------------
__device__ uint4  xp_g[(size_t)1024 * 64 * 32];      // x frag-packed: [band][k16][lane]
__device__ __half w1f16_g[(size_t)12 * DSZ * DIN];   // [mat*4+s][n=d][k]
__device__ __half w2f16_g[(size_t)4 * DSZ * DSZ];    // [s][n=e][k]
__device__ uint4  g1p_g[(size_t)4 * 1024 * 16 * 32]; // g1 frag-packed: [s][band][k16][lane]
__device__ __half dre_g[(size_t)4 * MTOT * DSZ];
__device__ __half dim_g[(size_t)4 * MTOT * DSZ];
__device__ float  omg_g[(size_t)4 * MTOT * DSZ];
__device__ float2 Aseg_g[512 * 256];
__device__ float2 Hseg_g[512 * 256];

// ---------------- helpers -------------------------------------------------------
__device__ __forceinline__ uint32_t pack_h2(float a, float b) {
    union { __half2 h; uint32_t u; } p;
    p.h = __halves2half2(__float2half_rn(a), __float2half_rn(b));
    return p.u;
}
__device__ __forceinline__ uint32_t smem_u32(const void* p) {
    uint32_t a;
    asm("{ .reg .u64 t; cvta.to.shared.u64 t, %1; cvt.u32.u64 %0, t; }" : "=r"(a) : "l"(p));
    return a;
}
__device__ __forceinline__ void cpa16(uint32_t dst, const void* src) {
    asm volatile("cp.async.cg.shared.global [%0], [%1], 16;" :: "r"(dst), "l"(src));
}
__device__ __forceinline__ void cpa_commit() {
    asm volatile("cp.async.commit_group;");
}
template<int N> __device__ __forceinline__ void cpa_wait() {
    asm volatile("cp.async.wait_group %0;" :: "n"(N));
}
__device__ __forceinline__ void ldsm4(uint32_t r[4], uint32_t addr) {
    asm volatile("ldmatrix.sync.aligned.m8n8.x4.shared.b16 {%0,%1,%2,%3}, [%4];"
        : "=r"(r[0]), "=r"(r[1]), "=r"(r[2]), "=r"(r[3]) : "r"(addr));
}
__device__ __forceinline__ void mma_f16u(float c[4], uint32_t a0, uint32_t a1, uint32_t a2, uint32_t a3,
                                         const uint32_t b[2]) {
    asm volatile("mma.sync.aligned.m16n8k16.row.col.f32.f16.f16.f32 "
        "{%0,%1,%2,%3}, {%4,%5,%6,%7}, {%8,%9}, {%0,%1,%2,%3};"
        : "+f"(c[0]), "+f"(c[1]), "+f"(c[2]), "+f"(c[3])
        : "r"(a0), "r"(a1), "r"(a2), "r"(a3), "r"(b[0]), "r"(b[1]));
}

// ---------------- GEMM 1: x @ {Wg1,Wdr,Wdi}; A frag-direct, B smem KCH=128 ------
__global__ __launch_bounds__(256, 2) void gemm1_k(
    const float* __restrict__ bg1, const float* __restrict__ bdr, const float* __restrict__ bdi)
{
    extern __shared__ char sm[];
    uint32_t s0 = smem_u32(sm);
    const int tid = threadIdx.x;

    const int mbase = blockIdx.x * 128;
    const int nb = blockIdx.y;                 // 0..23
    const int mat = nb >> 3;
    const int s = (nb >> 1) & 3;
    const int dbase = (nb & 1) * 128;

    const int lane = tid & 31, warp = tid >> 5;
    const int wm = warp & 3, wn = warp >> 2;
    const int band0 = (mbase >> 4) + wm * 2;

    const uint4* pA0 = xp_g + ((size_t)band0 * 64) * 32 + lane;
    const uint4* pA1 = xp_g + ((size_t)(band0 + 1) * 64) * 32 + lane;
    const __half* gB = w1f16_g + ((size_t)(mat * 4 + s) * DSZ + dbase) * DIN;
    const uint32_t bBase = (uint32_t)(wn * 64 + (lane & 7) + ((lane & 16) >> 1)) * LDR1
                         + ((lane >> 3) & 1) * 16;

    auto issueB = [&](int st, int k0) {
        uint32_t base = s0 + st * PLB1;
#pragma unroll
        for (int it = 0; it < 8; it++) {
            int q = tid + it * 256;
            int r = q >> 4, c = q & 15;
            cpa16(base + r * LDR1 + c * 16, gB + (size_t)r * DIN + k0 + c * 8);
        }
        cpa_commit();
    };

    float acc[2][8][4];
#pragma unroll
    for (int i = 0; i < 2; i++)
#pragma unroll
        for (int j = 0; j < 8; j++)
#pragma unroll
            for (int k = 0; k < 4; k++) acc[i][j][k] = 0.f;

    constexpr int NCH = DIN / KCH1;    // 8
    issueB(0, 0);
    issueB(1, KCH1);

    uint4 a0n = pA0[0];
    uint4 a1n = pA1[0];

    int st = 0;
    for (int ch = 0; ch < NCH; ch++) {
        if (ch >= NCH - 1) cpa_wait<0>(); else cpa_wait<1>();
        __syncthreads();
        if (ch + 2 < NCH) {
            int st2 = st + 2; if (st2 >= 3) st2 -= 3;
            issueB(st2, (ch + 2) * KCH1);
        }
        const uint4 a0c = a0n, a1c = a1n;
        if (ch + 1 < NCH) {
            a0n = pA0[(size_t)(ch + 1) * 8 * 32];
            a1n = pA1[(size_t)(ch + 1) * 8 * 32];
        }
        const uint32_t sb = s0 + st * PLB1;
#pragma unroll
        for (int ks = 0; ks < 8; ks++) {
            const int k16 = ch * 8 + ks;
            uint4 a0 = (ks == 0) ? a0c : pA0[(size_t)k16 * 32];
            uint4 a1 = (ks == 0) ? a1c : pA1[(size_t)k16 * 32];
            uint32_t bb[4][4];
#pragma unroll
            for (int nf4 = 0; nf4 < 4; nf4++)
                ldsm4(bb[nf4], sb + bBase + nf4 * (16 * LDR1) + ks * 32);
#pragma unroll
            for (int nf = 0; nf < 8; nf++) {
                const uint32_t* bp = &bb[nf >> 1][(nf & 1) * 2];
                mma_f16u(acc[0][nf], a0.x, a0.y, a0.z, a0.w, bp);
                mma_f16u(acc[1][nf], a1.x, a1.y, a1.z, a1.w, bp);
            }
        }
        if (++st >= 3) st = 0;
    }

    const int c0 = wn * 64 + (lane & 3) * 2;
    const float* bias = (mat == 0 ? bg1 : (mat == 1 ? bdr : bdi)) + s * DSZ + dbase;

    if (mat == 0) {
        uint4* gp = g1p_g + ((size_t)s * 1024 * 16) * 32;
#pragma unroll
        for (int mi = 0; mi < 2; mi++) {
            const int band = band0 + mi;
#pragma unroll
            for (int p = 0; p < 4; p++) {
                const int nf = 2 * p;
                const int col = c0 + nf * 8;
                float b0 = bias[col],      b1 = bias[col + 1];
                float b2 = bias[col + 8],  b3 = bias[col + 9];
                uint4 w;
                w.x = pack_h2(fmaxf(acc[mi][nf][0] + b0, 0.f),
                              fmaxf(acc[mi][nf][1] + b1, 0.f));
                w.y = pack_h2(fmaxf(acc[mi][nf][2] + b0, 0.f),
                              fmaxf(acc[mi][nf][3] + b1, 0.f));
                w.z = pack_h2(fmaxf(acc[mi][nf + 1][0] + b2, 0.f),
                              fmaxf(acc[mi][nf + 1][1] + b3, 0.f));
                w.w = pack_h2(fmaxf(acc[mi][nf + 1][2] + b2, 0.f),
                              fmaxf(acc[mi][nf + 1][3] + b3, 0.f));
                const int k16 = (dbase + wn * 64 + nf * 8) >> 4;
                gp[((size_t)band * 16 + k16) * 32 + lane] = w;
            }
        }
    } else {
        const int r0 = mbase + wm * 32 + (lane >> 2);
        __half* op = (mat == 1 ? dre_g : dim_g) + (size_t)s * MTOT * DSZ;
#pragma unroll
        for (int mi = 0; mi < 2; mi++)
#pragma unroll
            for (int nf = 0; nf < 8; nf++) {
                int col = c0 + nf * 8;
                float b0 = bias[col], b1 = bias[col + 1];
#pragma unroll
                for (int hh = 0; hh < 2; hh++) {
                    int r = r0 + mi * 16 + hh * 8;
                    union { __half2 h; uint32_t u; } pk;
                    pk.u = pack_h2(acc[mi][nf][hh * 2 + 0] + b0,
                                   acc[mi][nf][hh * 2 + 1] + b1);
                    *(__half2*)(op + (size_t)r * DSZ + dbase + col) = pk.h;
                }
            }
    }
}

// ---------------- GEMM 2: B resident once, 4 m-tiles per CTA, single wave -------
__global__ __launch_bounds__(256, 2) void gemm2_k(const float* __restrict__ bg2)
{
    extern __shared__ char sm[];
    uint32_t s0 = smem_u32(sm);
    const int tid = threadIdx.x;

    const int mgrp = blockIdx.x;               // 0..31 -> 4 m-tiles each
    const int s = blockIdx.y >> 1;
    const int dbase = (blockIdx.y & 1) * 128;

    const int lane = tid & 31, warp = tid >> 5;
    const int wm = warp & 3, wn = warp >> 2;

    const __half* gB = w2f16_g + ((size_t)s * DSZ + dbase) * DSZ;

    // single-shot load of entire B tile [128 n-rows x 256 k-halfs]
#pragma unroll
    for (int it = 0; it < 16; it++) {
        int q = tid + it * 256;
        int r = q >> 5, c = q & 31;
        cpa16(s0 + r * LDR2 + c * 16, gB + (size_t)r * DSZ + c * 8);
    }
    cpa_commit();

    const uint32_t bBase = (uint32_t)(wn * 64 + (lane & 7) + ((lane & 16) >> 1)) * LDR2
                         + ((lane >> 3) & 1) * 16;
    const int c0 = wn * 64 + (lane & 3) * 2;
    const float* bias = bg2 + s * DSZ + dbase;
    float* opb = omg_g + (size_t)s * MTOT * DSZ;

    cpa_wait<0>();
    __syncthreads();

    for (int mt = 0; mt < 4; mt++) {
        const int mbase = (mgrp * 4 + mt) * 128;
        const int band0 = (mbase >> 4) + wm * 2;
        const uint4* pA0 = g1p_g + ((size_t)(s * 1024 + band0) * 16) * 32 + lane;
        const uint4* pA1 = g1p_g + ((size_t)(s * 1024 + band0 + 1) * 16) * 32 + lane;

        float acc[2][8][4];
#pragma unroll
        for (int i = 0; i < 2; i++)
#pragma unroll
            for (int j = 0; j < 8; j++)
#pragma unroll
                for (int k = 0; k < 4; k++) acc[i][j][k] = 0.f;

#pragma unroll
        for (int k16 = 0; k16 < 16; k16++) {
            uint4 a0 = pA0[(size_t)k16 * 32];
            uint4 a1 = pA1[(size_t)k16 * 32];
            uint32_t bb[4][4];
#pragma unroll
            for (int nf4 = 0; nf4 < 4; nf4++)
                ldsm4(bb[nf4], s0 + bBase + nf4 * (16 * LDR2) + k16 * 32);
#pragma unroll
            for (int nf = 0; nf < 8; nf++) {
                const uint32_t* bp = &bb[nf >> 1][(nf & 1) * 2];
                mma_f16u(acc[0][nf], a0.x, a0.y, a0.z, a0.w, bp);
                mma_f16u(acc[1][nf], a1.x, a1.y, a1.z, a1.w, bp);
            }
        }

        const int r0 = mbase + wm * 32 + (lane >> 2);
#pragma unroll
        for (int mi = 0; mi < 2; mi++)
#pragma unroll
            for (int nf = 0; nf < 8; nf++) {
                int col = c0 + nf * 8;
                float b0 = bias[col], b1 = bias[col + 1];
#pragma unroll
                for (int hh = 0; hh < 2; hh++) {
                    int r = r0 + mi * 16 + hh * 8;
                    float2 v;
                    v.x = 1.0f / (1.0f + expf(acc[mi][nf][hh * 2 + 0] + b0));
                    v.y = 1.0f / (1.0f + expf(acc[mi][nf][hh * 2 + 1] + b1));
                    *(float2*)(opb + (size_t)r * DSZ + dbase + col) = v;
                }
            }
    }
}

// ---------------- conversion kernels -------------------------------------------
__global__ __launch_bounds__(256) void conv_x_k(const float* __restrict__ x) {
    const size_t idx = (size_t)blockIdx.x * 256 + threadIdx.x;
    const int lane = idx & 31;
    const int k16  = ((int)(idx >> 5)) & 63;
    const int band = (int)(idx >> 11);
    const int g = lane >> 2, t = lane & 3;
    const size_t r0 = (size_t)(band * 16 + g) * DIN;
    const size_t r8 = r0 + 8 * DIN;
    const int col = k16 * 16 + 2 * t;
    float2 v00 = *(const float2*)(x + r0 + col);
    float2 v10 = *(const float2*)(x + r8 + col);
    float2 v01 = *(const float2*)(x + r0 + col + 8);
    float2 v11 = *(const float2*)(x + r8 + col + 8);
    uint4 w;
    w.x = pack_h2(v00.x, v00.y);
    w.y = pack_h2(v10.x, v10.y);
    w.z = pack_h2(v01.x, v01.y);
    w.w = pack_h2(v11.x, v11.y);
    xp_g[idx] = w;
}

__global__ void conv_w_all_k(const float* __restrict__ Wg1,
                             const float* __restrict__ Wdr,
                             const float* __restrict__ Wdi,
                             const float* __restrict__ Wg2) {
    __shared__ float t[32][33];
    int z = blockIdx.z;
    const int kdim = (z < 12) ? DIN : DSZ;
    if (blockIdx.x * 32 >= kdim) return;
    const float* base = (z < 4 ? Wg1 : (z < 8 ? Wdr : (z < 12 ? Wdi : Wg2)));
    const float* sp = base + (size_t)(z & 3) * kdim * DSZ;
    int tx = threadIdx.x, ty = threadIdx.y;
    int k0 = blockIdx.x * 32, d0 = blockIdx.y * 32;
#pragma unroll
    for (int i = 0; i < 4; i++)
        t[ty + i * 8][tx] = sp[(size_t)(k0 + ty + i * 8) * DSZ + d0 + tx];
    __syncthreads();
    __half* oh = (z < 12) ? (w1f16_g + (size_t)z * DSZ * DIN)
                          : (w2f16_g + (size_t)(z - 12) * DSZ * DSZ);
#pragma unroll
    for (int i = 0; i < 4; i++) {
        int n = d0 + ty + i * 8, k = k0 + tx;
        oh[(size_t)n * kdim + k] = __float2half_rn(t[tx][ty + i * 8]);
    }
}

// ---------------- segmented scan (2 phases, 32 segments) ------------------------
struct ScanConsts { float abr[4], abi[4], bsc[4]; };

__global__ __launch_bounds__(256) void scan_p1(ScanConsts c) {
    const int idx = blockIdx.x;                // b*128 + s*32 + seg
    const int seg = idx & (NSEG - 1), s = (idx >> 5) & 3, b = idx >> 7;
    const int d = threadIdx.x;
    const float abr = c.abr[s], abi = c.abi[s], bs = c.bsc[s];
    const size_t base = ((size_t)s * MTOT + (size_t)b * 4096 + seg * TSEG) * DSZ + d;
    float Ar = 1.f, Ai = 0.f, Hr = 0.f, Hi = 0.f;
#pragma unroll 4
    for (int t = 0; t < TSEG; t++) {
        size_t off = base + (size_t)t * DSZ;
        float w  = omg_g[off];
        float xr = __half2float(dre_g[off]);
        float xi = __half2float(dim_g[off]);
        float ar = w * abr, ai = w * abi, wb = w * bs;
        float br = wb * xr, bi = wb * xi;
        float nHr = fmaf(ar, Hr, fmaf(-ai, Hi, br));
        float nHi = fmaf(ar, Hi, fmaf( ai, Hr, bi));
        float nAr = fmaf(ar, Ar, -ai * Ai);
        float nAi = fmaf(ar, Ai,  ai * Ar);
        Hr = nHr; Hi = nHi; Ar = nAr; Ai = nAi;
    }
    Aseg_g[idx * 256 + d] = make_float2(Ar, Ai);
    Hseg_g[idx * 256 + d] = make_float2(Hr, Hi);
}

__global__ __launch_bounds__(256) void scan_p3(float* __restrict__ out, ScanConsts c) {
    const int idx = blockIdx.x;
    const int seg = idx & (NSEG - 1), s = (idx >> 5) & 3, b = idx >> 7;
    const int d = threadIdx.x;
    const float abr = c.abr[s], abi = c.abi[s], bs = c.bsc[s];
    const size_t base = ((size_t)s * MTOT + (size_t)b * 4096 + seg * TSEG) * DSZ + d;

    float hr = 0.f, hi = 0.f;
    const int rowbase = idx - seg;
    for (int g = 0; g < seg; g++) {
        float2 A = Aseg_g[(rowbase + g) * 256 + d];
        float2 H = Hseg_g[(rowbase + g) * 256 + d];
        float nhr = fmaf(A.x, hr, fmaf(-A.y, hi, H.x));
        float nhi = fmaf(A.x, hi, fmaf( A.y, hr, H.y));
        hr = nhr; hi = nhi;
    }

    float* op = out + ((size_t)b * 4096 + seg * TSEG) * 2048 + (size_t)s * 512 + d;
#pragma unroll 4
    for (int t = 0; t < TSEG; t++) {
        size_t off = base + (size_t)t * DSZ;
        float w  = omg_g[off];
        float xr = __half2float(dre_g[off]);
        float xi = __half2float(dim_g[off]);
        float ar = w * abr, ai = w * abi, wb = w * bs;
        float br = wb * xr, bi = wb * xi;
        float nhr = fmaf(ar, hr, fmaf(-ai, hi, br));
        float nhi = fmaf(ar, hi, fmaf( ai, hr, bi));
        hr = nhr; hi = nhi;
        op[(size_t)t * 2048]       = hr;
        op[(size_t)t * 2048 + 256] = hi;
    }
}

// ---------------- host ----------------------------------------------------------
extern "C" void kernel_launch(void* const* d_in, const int* in_sizes, int n_in,
                              void* d_out, int out_size)
{
    const float* x   = (const float*)d_in[0];
    const float* Wg1 = (const float*)d_in[1];
    const float* bg1 = (const float*)d_in[2];
    const float* Wg2 = (const float*)d_in[3];
    const float* bg2 = (const float*)d_in[4];
    const float* Wdr = (const float*)d_in[5];
    const float* bdr = (const float*)d_in[6];
    const float* Wdi = (const float*)d_in[7];
    const float* bdi = (const float*)d_in[8];
    float* out = (float*)d_out;

    cudaFuncSetAttribute(gemm1_k, cudaFuncAttributeMaxDynamicSharedMemorySize, SMEM1);
    cudaFuncSetAttribute(gemm2_k, cudaFuncAttributeMaxDynamicSharedMemorySize, SMEM2);

    conv_x_k<<<8192, 256>>>(x);
    dim3 tb(32, 8);
    conv_w_all_k<<<dim3(32, 8, 16), tb>>>(Wg1, Wdr, Wdi, Wg2);

    gemm1_k<<<dim3(MTOT / 128, 24), 256, SMEM1>>>(bg1, bdr, bdi);
    gemm2_k<<<dim3(32, 8), 256, SMEM2>>>(bg2);

    ScanConsts c;
    const double r [4] = {1.0, 0.999, 0.9495, 0.9};
    const double th[4] = {0.0, 0.01,  0.505,  1.0};
    for (int s = 0; s < 4; s++) {
        c.abr[s] = (float)(r[s] * cos(th[s]));
        c.abi[s] = (float)(r[s] * sin(th[s]));
        c.bsc[s] = (float)((r[s] >= 1.0) ? (1.0 / 16.0) : (1.0 - r[s]));
    }
    scan_p1<<<512, 256>>>(c);
    scan_p3<<<512, 256>>>(out, c);
}